// round 12
// baseline (speedup 1.0000x reference)
#include <cuda_runtime.h>
#include <cuda_bf16.h>
#include <cstdint>

// Problem constants (match reference)
#define NPTS 200000
#define BATCH 4
#define CV 64
#define CI 256
#define HF 48
#define WF 160
#define HW (HF * WF)          // 7680
#define OUTW (CV + CI)        // 320

#define TR_BLOCKS 1920                      // 60 * 8 * 4 transpose tiles
#define META_BLOCKS ((NPTS + 255) / 256)    // 782
#define PTS_PER_BLOCK 16
#define GB_V ((NPTS + PTS_PER_BLOCK - 1) / PTS_PER_BLOCK)  // 12500 valid-type
#define GB_F GB_V                                          // 12500 fill-type

// Scratch: img_feats transposed to [B, H, W, C]; 31.4 MB, L2-resident.
__device__ float g_imgT[(size_t)BATCH * HW * CI];
// Per-point gather metadata (offset 0 / weight 0 for invalid corners).
__device__ int4   g_off[NPTS];
__device__ float4 g_w[NPTS];
// Validity compaction: counters + index lists.
__device__ int g_cnt[2];          // [0]=n_valid, [1]=n_invalid (memset to 0)
__device__ int g_vlist[NPTS];
__device__ int g_ilist[NPTS];

// ---------------------------------------------------------------------------
// Transpose tile: [B, C, H*W] -> [B, H*W, C], float4 both global sides.
// ---------------------------------------------------------------------------
__device__ __forceinline__ void transpose_tile(const float* __restrict__ img,
                                               int tileId, int t) {
    __shared__ float tile[32][129];
    const int px = tileId % 60;
    const int cy = (tileId / 60) % 8;
    const int b  = tileId / 480;
    const int p0 = px * 128;
    const int c0 = cy * 32;

    const float* src = img    + (size_t)b * CI * HW;
    float*       dst = g_imgT + (size_t)b * HW * CI;

    float4 v[4];
    int cc[4], qq[4];
    #pragma unroll
    for (int r = 0; r < 4; r++) {
        const int linear = r * 256 + t;
        cc[r] = linear >> 5;
        qq[r] = linear & 31;
        v[r] = __ldcs((const float4*)(src + (size_t)(c0 + cc[r]) * HW + p0 + qq[r] * 4));
    }
    #pragma unroll
    for (int r = 0; r < 4; r++) {
        tile[cc[r]][qq[r] * 4 + 0] = v[r].x;
        tile[cc[r]][qq[r] * 4 + 1] = v[r].y;
        tile[cc[r]][qq[r] * 4 + 2] = v[r].z;
        tile[cc[r]][qq[r] * 4 + 3] = v[r].w;
    }
    __syncthreads();

    #pragma unroll
    for (int r = 0; r < 4; r++) {
        const int linear = r * 256 + t;
        const int p  = linear >> 3;
        const int cq = linear & 7;
        float4 o;
        o.x = tile[cq * 4 + 0][p];
        o.y = tile[cq * 4 + 1][p];
        o.z = tile[cq * 4 + 2][p];
        o.w = tile[cq * 4 + 3][p];
        *(float4*)(dst + (size_t)(p0 + p) * CI + c0 + cq * 4) = o;
    }
}

// ---------------------------------------------------------------------------
// Meta: projection + weights + offsets, and validity-compacted lists.
// ---------------------------------------------------------------------------
__device__ __forceinline__ void meta_point(const float* __restrict__ points_mean,
                                           const int*   __restrict__ coors,
                                           const float* __restrict__ lidar2img,
                                           const int*   __restrict__ pad_shape,
                                           int n, int lane) {
    const bool active = (n < NPTS);
    bool valid = false;

    if (active) {
        const int b = __ldg(&coors[(size_t)n * 4]);

        const float px = __ldg(&points_mean[(size_t)n * 3 + 0]);
        const float py = __ldg(&points_mean[(size_t)n * 3 + 1]);
        const float pz = __ldg(&points_mean[(size_t)n * 3 + 2]);

        const float* M = lidar2img + (size_t)b * 16;
        const float p0 = __ldg(&M[0]) * px + __ldg(&M[1]) * py + __ldg(&M[2])  * pz + __ldg(&M[3]);
        const float p1 = __ldg(&M[4]) * px + __ldg(&M[5]) * py + __ldg(&M[6])  * pz + __ldg(&M[7]);
        const float p2 = __ldg(&M[8]) * px + __ldg(&M[9]) * py + __ldg(&M[10]) * pz + __ldg(&M[11]);

        const float z     = fmaxf(p2, 1e-5f);
        const float x_pix = p0 / z;
        const float y_pix = p1 / z;

        const float padH = (float)__ldg(&pad_shape[(size_t)b * 2 + 0]);
        const float padW = (float)__ldg(&pad_shape[(size_t)b * 2 + 1]);

        const float gx = x_pix / padW * 2.0f - 1.0f;
        const float gy = y_pix / padH * 2.0f - 1.0f;
        const float ix = (gx + 1.0f) * 0.5f * (float)(WF - 1);
        const float iy = (gy + 1.0f) * 0.5f * (float)(HF - 1);

        const float ix0f = floorf(ix);
        const float iy0f = floorf(iy);
        const float wx1 = ix - ix0f, wx0 = 1.0f - wx1;
        const float wy1 = iy - iy0f, wy0 = 1.0f - wy1;

        const int ix0 = (int)ix0f, iy0 = (int)iy0f;
        const int ix1 = ix0 + 1,   iy1 = iy0 + 1;

        const bool vx0 = (ix0 >= 0) & (ix0 < WF);
        const bool vx1 = (ix1 >= 0) & (ix1 < WF);
        const bool vy0 = (iy0 >= 0) & (iy0 < HF);
        const bool vy1 = (iy1 >= 0) & (iy1 < HF);

        const float w00 = (vy0 & vx0) ? (wy0 * wx0) : 0.0f;
        const float w01 = (vy0 & vx1) ? (wy0 * wx1) : 0.0f;
        const float w10 = (vy1 & vx0) ? (wy1 * wx0) : 0.0f;
        const float w11 = (vy1 & vx1) ? (wy1 * wx1) : 0.0f;

        const int bbase = b * HW * CI;
        int4 off;
        off.x = (w00 != 0.0f) ? bbase + (iy0 * WF + ix0) * CI : 0;
        off.y = (w01 != 0.0f) ? bbase + (iy0 * WF + ix1) * CI : 0;
        off.z = (w10 != 0.0f) ? bbase + (iy1 * WF + ix0) * CI : 0;
        off.w = (w11 != 0.0f) ? bbase + (iy1 * WF + ix1) * CI : 0;

        valid = ((w00 + w01) + (w10 + w11)) != 0.0f;  // weights >= 0

        if (valid) {               // only valid points need meta
            g_off[n] = off;
            g_w[n]   = make_float4(w00, w01, w10, w11);
        }
    }

    // warp-compacted list append
    const unsigned mv = __ballot_sync(0xffffffffu, active && valid);
    const unsigned mi = __ballot_sync(0xffffffffu, active && !valid);
    const unsigned ltmask = (1u << lane) - 1u;
    int baseV = 0, baseI = 0;
    if (lane == 0) {
        if (mv) baseV = atomicAdd(&g_cnt[0], __popc(mv));
        if (mi) baseI = atomicAdd(&g_cnt[1], __popc(mi));
    }
    baseV = __shfl_sync(0xffffffffu, baseV, 0);
    baseI = __shfl_sync(0xffffffffu, baseI, 0);
    if (active) {
        if (valid) g_vlist[baseV + __popc(mv & ltmask)] = n;
        else       g_ilist[baseI + __popc(mi & ltmask)] = n;
    }
}

// ---------------------------------------------------------------------------
// Kernel A: fused transpose + meta/lists.
// ---------------------------------------------------------------------------
__global__ __launch_bounds__(256)
void prep_kernel(const float* __restrict__ img,
                 const float* __restrict__ points_mean,
                 const int*   __restrict__ coors,
                 const float* __restrict__ lidar2img,
                 const int*   __restrict__ pad_shape) {
    if (blockIdx.x < TR_BLOCKS) {
        transpose_tile(img, blockIdx.x, threadIdx.x);
    } else {
        const int n = (blockIdx.x - TR_BLOCKS) * 256 + threadIdx.x;
        meta_point(points_mean, coors, lidar2img, pad_shape, n, threadIdx.x & 31);
    }
}

// per-corner warp-uniform skip (measured fastest, R8)
__device__ __forceinline__ void corner_acc(int off, float w,
                                           int off0, int off1,
                                           float4& a0, float4& a1) {
    if (w != 0.0f) {
        const float* row = g_imgT + off;
        float4 v0 = *(const float4*)(row + off0);
        float4 v1 = *(const float4*)(row + off1);
        a0.x += w * v0.x; a0.y += w * v0.y; a0.z += w * v0.z; a0.w += w * v0.w;
        a1.x += w * v1.x; a1.y += w * v1.y; a1.z += w * v1.z; a1.w += w * v1.w;
    }
}

// ---------------------------------------------------------------------------
// Valid block: 16 compacted valid points; full rows (voxel + gathered feats).
// ---------------------------------------------------------------------------
__device__ __forceinline__ void valid_block(const float* __restrict__ voxel_feats,
                                            float* __restrict__ out,
                                            int blockId, int t) {
    __shared__ int    s_idx[PTS_PER_BLOCK];
    __shared__ int4   s_off[PTS_PER_BLOCK];
    __shared__ float4 s_w[PTS_PER_BLOCK];

    const int nv   = __ldg(&g_cnt[0]);
    const int base = blockId * PTS_PER_BLOCK;
    if (base >= nv) return;

    if (t < PTS_PER_BLOCK)
        s_idx[t] = (base + t < nv) ? __ldg(&g_vlist[base + t]) : -1;
    __syncthreads();
    if (t < PTS_PER_BLOCK) {
        const int ix = s_idx[t];
        s_off[t] = (ix >= 0) ? __ldg(&g_off[ix]) : make_int4(0, 0, 0, 0);
    } else if (t < 2 * PTS_PER_BLOCK) {
        const int ix = s_idx[t - PTS_PER_BLOCK];
        s_w[t - PTS_PER_BLOCK] = (ix >= 0) ? __ldg(&g_w[ix])
                                           : make_float4(0.f, 0.f, 0.f, 0.f);
    }
    __syncthreads();

    const int warp = t >> 5;
    const int lane = t & 31;
    const int off0 = lane * 4;
    const int off1 = 128 + lane * 4;

    // voxel rows: full warp, lanes split 16/16 over the warp's 2 points
    {
        const int sub = lane >> 4;
        const int q   = lane & 15;
        const int nvx = s_idx[warp * 2 + sub];
        if (nvx >= 0) {
            float4 v = __ldcs((const float4*)(voxel_feats + (size_t)nvx * CV) + q);
            __stcs((float4*)(out + (size_t)nvx * OUTW) + q, v);
        }
    }

    #pragma unroll
    for (int i = 0; i < 2; i++) {
        const int li = warp * 2 + i;
        const int n  = s_idx[li];
        if (n < 0) continue;

        const int4   off = s_off[li];
        const float4 w   = s_w[li];

        float4 a0 = make_float4(0.f, 0.f, 0.f, 0.f);
        float4 a1 = make_float4(0.f, 0.f, 0.f, 0.f);

        corner_acc(off.x, w.x, off0, off1, a0, a1);
        corner_acc(off.y, w.y, off0, off1, a0, a1);
        corner_acc(off.z, w.z, off0, off1, a0, a1);
        corner_acc(off.w, w.w, off0, off1, a0, a1);

        float4* orow = (float4*)(out + (size_t)n * OUTW);
        __stcs(&orow[16 + lane],      a0);
        __stcs(&orow[16 + 32 + lane], a1);
    }
}

// ---------------------------------------------------------------------------
// Fill block: 16 compacted invalid points; voxel row + zero feats.
// Pure streaming stores — no meta, no gathers.
// ---------------------------------------------------------------------------
__device__ __forceinline__ void fill_block(const float* __restrict__ voxel_feats,
                                           float* __restrict__ out,
                                           int blockId, int t) {
    __shared__ int s_idx[PTS_PER_BLOCK];

    const int ni   = __ldg(&g_cnt[1]);
    const int base = blockId * PTS_PER_BLOCK;
    if (base >= ni) return;

    if (t < PTS_PER_BLOCK)
        s_idx[t] = (base + t < ni) ? __ldg(&g_ilist[base + t]) : -1;
    __syncthreads();

    const int warp = t >> 5;
    const int lane = t & 31;
    const float4 zero = make_float4(0.f, 0.f, 0.f, 0.f);

    // voxel rows: lanes split 16/16 over the warp's 2 points
    {
        const int sub = lane >> 4;
        const int q   = lane & 15;
        const int nvx = s_idx[warp * 2 + sub];
        if (nvx >= 0) {
            float4 v = __ldcs((const float4*)(voxel_feats + (size_t)nvx * CV) + q);
            __stcs((float4*)(out + (size_t)nvx * OUTW) + q, v);
        }
    }

    #pragma unroll
    for (int i = 0; i < 2; i++) {
        const int n = s_idx[warp * 2 + i];
        if (n < 0) continue;
        float4* orow = (float4*)(out + (size_t)n * OUTW);
        __stcs(&orow[16 + lane],      zero);
        __stcs(&orow[16 + 32 + lane], zero);
    }
}

// ---------------------------------------------------------------------------
// Kernel B: valid-type blocks + fill-type blocks.
// ---------------------------------------------------------------------------
__global__ __launch_bounds__(256)
void gather_kernel(const float* __restrict__ voxel_feats,
                   float* __restrict__ out) {
    if (blockIdx.x < GB_V) {
        valid_block(voxel_feats, out, blockIdx.x, threadIdx.x);
    } else {
        fill_block(voxel_feats, out, blockIdx.x - GB_V, threadIdx.x);
    }
}

// ---------------------------------------------------------------------------
extern "C" void kernel_launch(void* const* d_in, const int* in_sizes, int n_in,
                              void* d_out, int out_size) {
    const float* points_mean = (const float*)d_in[0];
    // d_in[1] = mask (unused by reference)
    const float* voxel_feats = (const float*)d_in[2];
    const int*   coors       = (const int*)  d_in[3];
    const float* img_feats   = (const float*)d_in[4];
    const float* lidar2img   = (const float*)d_in[5];
    const int*   pad_shape   = (const int*)  d_in[6];
    float*       out         = (float*)d_out;

    // reset list counters (graph-capturable memset, no allocation)
    void* cntAddr = nullptr;
    cudaGetSymbolAddress(&cntAddr, g_cnt);
    cudaMemsetAsync(cntAddr, 0, 2 * sizeof(int));

    // A: transpose + meta/lists
    prep_kernel<<<TR_BLOCKS + META_BLOCKS, 256>>>(
        img_feats, points_mean, coors, lidar2img, pad_shape);

    // B: compacted valid gathers + invalid zero-fill (+ voxel rows)
    gather_kernel<<<GB_V + GB_F, 256>>>(voxel_feats, out);
}

// round 13
// speedup vs baseline: 1.2086x; 1.2086x over previous
#include <cuda_runtime.h>
#include <cuda_bf16.h>
#include <cstdint>

// Problem constants (match reference)
#define NPTS 200000
#define BATCH 4
#define CV 64
#define CI 256
#define HF 48
#define WF 160
#define HW (HF * WF)          // 7680
#define OUTW (CV + CI)        // 320

#define TR_BLOCKS 1920                      // 60 * 8 * 4 transpose tiles
#define META_BLOCKS ((NPTS + 255) / 256)    // 782
#define PTS_PER_BLOCK 16                    // gather: 8 warps x 2 points
#define GATHER_BLOCKS (NPTS / PTS_PER_BLOCK)  // 12500
#define VOX_BLOCKS 3125                     // voxel copy: 3.2M float4 / 1024
// 12500 : 3125 = 4 : 1  ->  interleave with period 5 (15625 = 5 * 3125)

// Scratch: img_feats transposed to [B, H, W, C]; 31.4 MB, L2-resident.
__device__ float g_imgT[(size_t)BATCH * HW * CI];
// Per-point gather metadata (offset 0 / weight 0 for invalid corners).
__device__ int4   g_off[NPTS];
__device__ float4 g_w[NPTS];

// ---------------------------------------------------------------------------
// Transpose tile: [B, C, H*W] -> [B, H*W, C], float4 both global sides.
// ---------------------------------------------------------------------------
__device__ __forceinline__ void transpose_tile(const float* __restrict__ img,
                                               int tileId, int t) {
    __shared__ float tile[32][129];
    const int px = tileId % 60;
    const int cy = (tileId / 60) % 8;
    const int b  = tileId / 480;
    const int p0 = px * 128;
    const int c0 = cy * 32;

    const float* src = img    + (size_t)b * CI * HW;
    float*       dst = g_imgT + (size_t)b * HW * CI;

    float4 v[4];
    int cc[4], qq[4];
    #pragma unroll
    for (int r = 0; r < 4; r++) {
        const int linear = r * 256 + t;
        cc[r] = linear >> 5;
        qq[r] = linear & 31;
        v[r] = __ldcs((const float4*)(src + (size_t)(c0 + cc[r]) * HW + p0 + qq[r] * 4));
    }
    #pragma unroll
    for (int r = 0; r < 4; r++) {
        tile[cc[r]][qq[r] * 4 + 0] = v[r].x;
        tile[cc[r]][qq[r] * 4 + 1] = v[r].y;
        tile[cc[r]][qq[r] * 4 + 2] = v[r].z;
        tile[cc[r]][qq[r] * 4 + 3] = v[r].w;
    }
    __syncthreads();

    #pragma unroll
    for (int r = 0; r < 4; r++) {
        const int linear = r * 256 + t;
        const int p  = linear >> 3;
        const int cq = linear & 7;
        float4 o;
        o.x = tile[cq * 4 + 0][p];
        o.y = tile[cq * 4 + 1][p];
        o.z = tile[cq * 4 + 2][p];
        o.w = tile[cq * 4 + 3][p];
        *(float4*)(dst + (size_t)(p0 + p) * CI + c0 + cq * 4) = o;
    }
}

// ---------------------------------------------------------------------------
// Meta: per-point projection, ONE thread per point.
// ---------------------------------------------------------------------------
__device__ __forceinline__ void meta_point(const float* __restrict__ points_mean,
                                           const int*   __restrict__ coors,
                                           const float* __restrict__ lidar2img,
                                           const int*   __restrict__ pad_shape,
                                           int n) {
    const int b = __ldg(&coors[(size_t)n * 4]);

    const float px = __ldg(&points_mean[(size_t)n * 3 + 0]);
    const float py = __ldg(&points_mean[(size_t)n * 3 + 1]);
    const float pz = __ldg(&points_mean[(size_t)n * 3 + 2]);

    const float* M = lidar2img + (size_t)b * 16;
    const float p0 = __ldg(&M[0]) * px + __ldg(&M[1]) * py + __ldg(&M[2])  * pz + __ldg(&M[3]);
    const float p1 = __ldg(&M[4]) * px + __ldg(&M[5]) * py + __ldg(&M[6])  * pz + __ldg(&M[7]);
    const float p2 = __ldg(&M[8]) * px + __ldg(&M[9]) * py + __ldg(&M[10]) * pz + __ldg(&M[11]);

    const float z     = fmaxf(p2, 1e-5f);
    const float x_pix = p0 / z;
    const float y_pix = p1 / z;

    const float padH = (float)__ldg(&pad_shape[(size_t)b * 2 + 0]);
    const float padW = (float)__ldg(&pad_shape[(size_t)b * 2 + 1]);

    const float gx = x_pix / padW * 2.0f - 1.0f;
    const float gy = y_pix / padH * 2.0f - 1.0f;
    const float ix = (gx + 1.0f) * 0.5f * (float)(WF - 1);
    const float iy = (gy + 1.0f) * 0.5f * (float)(HF - 1);

    const float ix0f = floorf(ix);
    const float iy0f = floorf(iy);
    const float wx1 = ix - ix0f, wx0 = 1.0f - wx1;
    const float wy1 = iy - iy0f, wy0 = 1.0f - wy1;

    const int ix0 = (int)ix0f, iy0 = (int)iy0f;
    const int ix1 = ix0 + 1,   iy1 = iy0 + 1;

    const bool vx0 = (ix0 >= 0) & (ix0 < WF);
    const bool vx1 = (ix1 >= 0) & (ix1 < WF);
    const bool vy0 = (iy0 >= 0) & (iy0 < HF);
    const bool vy1 = (iy1 >= 0) & (iy1 < HF);

    const float w00 = (vy0 & vx0) ? (wy0 * wx0) : 0.0f;
    const float w01 = (vy0 & vx1) ? (wy0 * wx1) : 0.0f;
    const float w10 = (vy1 & vx0) ? (wy1 * wx0) : 0.0f;
    const float w11 = (vy1 & vx1) ? (wy1 * wx1) : 0.0f;

    const int bbase = b * HW * CI;
    int4 off;
    off.x = (w00 != 0.0f) ? bbase + (iy0 * WF + ix0) * CI : 0;
    off.y = (w01 != 0.0f) ? bbase + (iy0 * WF + ix1) * CI : 0;
    off.z = (w10 != 0.0f) ? bbase + (iy1 * WF + ix0) * CI : 0;
    off.w = (w11 != 0.0f) ? bbase + (iy1 * WF + ix1) * CI : 0;

    g_off[n] = off;
    g_w[n]   = make_float4(w00, w01, w10, w11);
}

// ---------------------------------------------------------------------------
// Kernel A: transpose + meta (gather's true dependencies; measured ~3 us).
// ---------------------------------------------------------------------------
__global__ __launch_bounds__(256)
void prep_kernel(const float* __restrict__ img,
                 const float* __restrict__ points_mean,
                 const int*   __restrict__ coors,
                 const float* __restrict__ lidar2img,
                 const int*   __restrict__ pad_shape) {
    if (blockIdx.x < TR_BLOCKS) {
        transpose_tile(img, blockIdx.x, threadIdx.x);
    } else {
        const int n = (blockIdx.x - TR_BLOCKS) * 256 + threadIdx.x;
        if (n < NPTS)
            meta_point(points_mean, coors, lidar2img, pad_shape, n);
    }
}

// per-corner warp-uniform skip (measured fastest variant, R8)
__device__ __forceinline__ void corner_acc(int off, float w,
                                           int off0, int off1,
                                           float4& a0, float4& a1) {
    if (w != 0.0f) {
        const float* row = g_imgT + off;
        float4 v0 = *(const float4*)(row + off0);
        float4 v1 = *(const float4*)(row + off1);
        a0.x += w * v0.x; a0.y += w * v0.y; a0.z += w * v0.z; a0.w += w * v0.w;
        a1.x += w * v1.x; a1.y += w * v1.y; a1.z += w * v1.z; a1.w += w * v1.w;
    }
}

// ---------------------------------------------------------------------------
// Gather block body: 16 points, 8 warps x 2 points, meta staged in smem.
// (Verbatim R8 structure — the measured-fastest gather.)
// ---------------------------------------------------------------------------
__device__ __forceinline__ void gather_block(float* __restrict__ out,
                                             int blockId, int t) {
    __shared__ int4   s_off[PTS_PER_BLOCK];
    __shared__ float4 s_w[PTS_PER_BLOCK];

    const int base = blockId * PTS_PER_BLOCK;

    if (t < PTS_PER_BLOCK) {
        s_off[t] = __ldg(&g_off[base + t]);
    } else if (t < 2 * PTS_PER_BLOCK) {
        s_w[t - PTS_PER_BLOCK] = __ldg(&g_w[base + t - PTS_PER_BLOCK]);
    }
    __syncthreads();

    const int warp = t >> 5;   // 0..7
    const int lane = t & 31;
    const int off0 = lane * 4;
    const int off1 = 128 + lane * 4;

    #pragma unroll
    for (int i = 0; i < 2; i++) {
        const int li = warp * 2 + i;   // 0..15
        const int n  = base + li;      // NPTS % 16 == 0 -> in bounds

        const int4   off = s_off[li];  // LDS broadcast
        const float4 w   = s_w[li];

        float4 a0 = make_float4(0.f, 0.f, 0.f, 0.f);
        float4 a1 = make_float4(0.f, 0.f, 0.f, 0.f);

        corner_acc(off.x, w.x, off0, off1, a0, a1);
        corner_acc(off.y, w.y, off0, off1, a0, a1);
        corner_acc(off.z, w.z, off0, off1, a0, a1);
        corner_acc(off.w, w.w, off0, off1, a0, a1);

        float4* orow = (float4*)(out + (size_t)n * OUTW);
        __stcs(&orow[16 + lane],      a0);
        __stcs(&orow[16 + 32 + lane], a1);
    }
}

// ---------------------------------------------------------------------------
// Voxel copy block body: pure-BW stream.
// ---------------------------------------------------------------------------
__device__ __forceinline__ void voxel_copy(const float* __restrict__ voxel_feats,
                                           float* __restrict__ out,
                                           int blockId, int t) {
    const float4* src = (const float4*)voxel_feats;
    #pragma unroll
    for (int r = 0; r < 4; r++) {
        const int idx = blockId * 1024 + r * 256 + t;   // < 3.2M
        const int n = idx >> 4;
        const int q = idx & 15;
        float4 v = __ldcs(&src[idx]);
        __stcs((float4*)(out + (size_t)n * OUTW) + q, v);
    }
}

// ---------------------------------------------------------------------------
// Kernel B: gather + voxel copy, INTERLEAVED 4:1 so every wave carries both
// latency-bound gather blocks and pure-BW voxel blocks (R11 appended the
// voxel blocks at the tail, which just serialized them).
// grid = 15625 = 5 * 3125; blockIdx % 5 == 4 -> voxel, else gather.
// ---------------------------------------------------------------------------
__global__ __launch_bounds__(256)
void gather_kernel(const float* __restrict__ voxel_feats,
                   float* __restrict__ out) {
    const int grp = blockIdx.x / 5;
    const int rem = blockIdx.x % 5;
    if (rem == 4) {
        voxel_copy(voxel_feats, out, grp, threadIdx.x);          // 3125 blocks
    } else {
        gather_block(out, grp * 4 + rem, threadIdx.x);           // 12500 blocks
    }
}

// ---------------------------------------------------------------------------
extern "C" void kernel_launch(void* const* d_in, const int* in_sizes, int n_in,
                              void* d_out, int out_size) {
    const float* points_mean = (const float*)d_in[0];
    // d_in[1] = mask (unused by reference)
    const float* voxel_feats = (const float*)d_in[2];
    const int*   coors       = (const int*)  d_in[3];
    const float* img_feats   = (const float*)d_in[4];
    const float* lidar2img   = (const float*)d_in[5];
    const int*   pad_shape   = (const int*)  d_in[6];
    float*       out         = (float*)d_out;

    // A: transpose + projection meta
    prep_kernel<<<TR_BLOCKS + META_BLOCKS, 256>>>(
        img_feats, points_mean, coors, lidar2img, pad_shape);

    // B: gather + interleaved voxel copy
    gather_kernel<<<GATHER_BLOCKS + VOX_BLOCKS, 256>>>(voxel_feats, out);
}

// round 14
// speedup vs baseline: 1.2528x; 1.0366x over previous
#include <cuda_runtime.h>
#include <cuda_bf16.h>
#include <cstdint>

// Problem constants (match reference)
#define NPTS 200000
#define BATCH 4
#define CV 64
#define CI 256
#define HF 48
#define WF 160
#define HW (HF * WF)          // 7680
#define OUTW (CV + CI)        // 320

#define TR_BLOCKS 1920                      // 60 * 8 * 4 transpose tiles
#define VOX_BLOCKS 3125                     // voxel copy: 3.2M float4 / 1024
#define META_BLOCKS ((NPTS + 255) / 256)    // 782
#define PTS_PER_BLOCK 64                    // gather: 8 warps x 2 pts x 4 iters
#define GATHER_BLOCKS (NPTS / PTS_PER_BLOCK)  // 3125

// Scratch: img_feats transposed to [B, H, W, C]; 31.4 MB, L2-resident.
__device__ float g_imgT[(size_t)BATCH * HW * CI];
// Per-point gather metadata (offset 0 / weight 0 for invalid corners).
__device__ int4   g_off[NPTS];
__device__ float4 g_w[NPTS];

// ---------------------------------------------------------------------------
// Transpose tile: [B, C, H*W] -> [B, H*W, C], float4 both global sides.
// ---------------------------------------------------------------------------
__device__ __forceinline__ void transpose_tile(const float* __restrict__ img,
                                               int tileId, int t) {
    __shared__ float tile[32][129];
    const int px = tileId % 60;
    const int cy = (tileId / 60) % 8;
    const int b  = tileId / 480;
    const int p0 = px * 128;
    const int c0 = cy * 32;

    const float* src = img    + (size_t)b * CI * HW;
    float*       dst = g_imgT + (size_t)b * HW * CI;

    float4 v[4];
    int cc[4], qq[4];
    #pragma unroll
    for (int r = 0; r < 4; r++) {
        const int linear = r * 256 + t;
        cc[r] = linear >> 5;
        qq[r] = linear & 31;
        v[r] = __ldcs((const float4*)(src + (size_t)(c0 + cc[r]) * HW + p0 + qq[r] * 4));
    }
    #pragma unroll
    for (int r = 0; r < 4; r++) {
        tile[cc[r]][qq[r] * 4 + 0] = v[r].x;
        tile[cc[r]][qq[r] * 4 + 1] = v[r].y;
        tile[cc[r]][qq[r] * 4 + 2] = v[r].z;
        tile[cc[r]][qq[r] * 4 + 3] = v[r].w;
    }
    __syncthreads();

    #pragma unroll
    for (int r = 0; r < 4; r++) {
        const int linear = r * 256 + t;
        const int p  = linear >> 3;
        const int cq = linear & 7;
        float4 o;
        o.x = tile[cq * 4 + 0][p];
        o.y = tile[cq * 4 + 1][p];
        o.z = tile[cq * 4 + 2][p];
        o.w = tile[cq * 4 + 3][p];
        *(float4*)(dst + (size_t)(p0 + p) * CI + c0 + cq * 4) = o;
    }
}

// ---------------------------------------------------------------------------
// Voxel copy: voxel_feats row -> first 64 floats of out row (pure BW).
// ---------------------------------------------------------------------------
__device__ __forceinline__ void voxel_copy(const float* __restrict__ voxel_feats,
                                           float* __restrict__ out,
                                           int blockId, int t) {
    const float4* src = (const float4*)voxel_feats;
    #pragma unroll
    for (int r = 0; r < 4; r++) {
        const int idx = blockId * 1024 + r * 256 + t;   // < 3.2M
        const int n = idx >> 4;
        const int q = idx & 15;
        float4 v = __ldcs(&src[idx]);
        __stcs((float4*)(out + (size_t)n * OUTW) + q, v);
    }
}

// ---------------------------------------------------------------------------
// Meta: per-point projection, ONE thread per point.
// ---------------------------------------------------------------------------
__device__ __forceinline__ void meta_point(const float* __restrict__ points_mean,
                                           const int*   __restrict__ coors,
                                           const float* __restrict__ lidar2img,
                                           const int*   __restrict__ pad_shape,
                                           int n) {
    const int b = __ldg(&coors[(size_t)n * 4]);

    const float px = __ldg(&points_mean[(size_t)n * 3 + 0]);
    const float py = __ldg(&points_mean[(size_t)n * 3 + 1]);
    const float pz = __ldg(&points_mean[(size_t)n * 3 + 2]);

    const float* M = lidar2img + (size_t)b * 16;
    const float p0 = __ldg(&M[0]) * px + __ldg(&M[1]) * py + __ldg(&M[2])  * pz + __ldg(&M[3]);
    const float p1 = __ldg(&M[4]) * px + __ldg(&M[5]) * py + __ldg(&M[6])  * pz + __ldg(&M[7]);
    const float p2 = __ldg(&M[8]) * px + __ldg(&M[9]) * py + __ldg(&M[10]) * pz + __ldg(&M[11]);

    const float z     = fmaxf(p2, 1e-5f);
    const float x_pix = p0 / z;
    const float y_pix = p1 / z;

    const float padH = (float)__ldg(&pad_shape[(size_t)b * 2 + 0]);
    const float padW = (float)__ldg(&pad_shape[(size_t)b * 2 + 1]);

    const float gx = x_pix / padW * 2.0f - 1.0f;
    const float gy = y_pix / padH * 2.0f - 1.0f;
    const float ix = (gx + 1.0f) * 0.5f * (float)(WF - 1);
    const float iy = (gy + 1.0f) * 0.5f * (float)(HF - 1);

    const float ix0f = floorf(ix);
    const float iy0f = floorf(iy);
    const float wx1 = ix - ix0f, wx0 = 1.0f - wx1;
    const float wy1 = iy - iy0f, wy0 = 1.0f - wy1;

    const int ix0 = (int)ix0f, iy0 = (int)iy0f;
    const int ix1 = ix0 + 1,   iy1 = iy0 + 1;

    const bool vx0 = (ix0 >= 0) & (ix0 < WF);
    const bool vx1 = (ix1 >= 0) & (ix1 < WF);
    const bool vy0 = (iy0 >= 0) & (iy0 < HF);
    const bool vy1 = (iy1 >= 0) & (iy1 < HF);

    const float w00 = (vy0 & vx0) ? (wy0 * wx0) : 0.0f;
    const float w01 = (vy0 & vx1) ? (wy0 * wx1) : 0.0f;
    const float w10 = (vy1 & vx0) ? (wy1 * wx0) : 0.0f;
    const float w11 = (vy1 & vx1) ? (wy1 * wx1) : 0.0f;

    const int bbase = b * HW * CI;
    int4 off;
    off.x = (w00 != 0.0f) ? bbase + (iy0 * WF + ix0) * CI : 0;
    off.y = (w01 != 0.0f) ? bbase + (iy0 * WF + ix1) * CI : 0;
    off.z = (w10 != 0.0f) ? bbase + (iy1 * WF + ix0) * CI : 0;
    off.w = (w11 != 0.0f) ? bbase + (iy1 * WF + ix1) * CI : 0;

    g_off[n] = off;
    g_w[n]   = make_float4(w00, w01, w10, w11);
}

// ---------------------------------------------------------------------------
// Kernel A: fused transpose + voxel copy + meta (R8 arrangement — best total).
// ---------------------------------------------------------------------------
__global__ __launch_bounds__(256)
void prep_kernel(const float* __restrict__ img,
                 const float* __restrict__ points_mean,
                 const int*   __restrict__ coors,
                 const float* __restrict__ lidar2img,
                 const int*   __restrict__ pad_shape,
                 const float* __restrict__ voxel_feats,
                 float*       __restrict__ out) {
    if (blockIdx.x < TR_BLOCKS) {
        transpose_tile(img, blockIdx.x, threadIdx.x);
    } else if (blockIdx.x < TR_BLOCKS + VOX_BLOCKS) {
        voxel_copy(voxel_feats, out, blockIdx.x - TR_BLOCKS, threadIdx.x);
    } else {
        const int n = (blockIdx.x - TR_BLOCKS - VOX_BLOCKS) * 256 + threadIdx.x;
        if (n < NPTS)
            meta_point(points_mean, coors, lidar2img, pad_shape, n);
    }
}

// per-corner warp-uniform skip (measured fastest variant, R8)
__device__ __forceinline__ void corner_acc(int off, float w,
                                           int off0, int off1,
                                           float4& a0, float4& a1) {
    if (w != 0.0f) {
        const float* row = g_imgT + off;
        float4 v0 = *(const float4*)(row + off0);
        float4 v1 = *(const float4*)(row + off1);
        a0.x += w * v0.x; a0.y += w * v0.y; a0.z += w * v0.z; a0.w += w * v0.w;
        a1.x += w * v1.x; a1.y += w * v1.y; a1.z += w * v1.z; a1.w += w * v1.w;
    }
}

// ---------------------------------------------------------------------------
// Kernel B: gather + point-feat write. Block owns 64 points: meta for all 64
// staged in smem with ONE syncthreads, then 4 barrier-free unrolled
// iterations (warp -> 2 points each). Iterations are independent, so loads
// of iteration i+1 overlap the tail of iteration i (software pipelining)
// while per-iteration register state stays flat.
// ---------------------------------------------------------------------------
__global__ __launch_bounds__(256)
void gather_kernel(float* __restrict__ out) {
    __shared__ int4   s_off[PTS_PER_BLOCK];
    __shared__ float4 s_w[PTS_PER_BLOCK];

    const int t    = threadIdx.x;
    const int base = blockIdx.x * PTS_PER_BLOCK;

    if (t < PTS_PER_BLOCK) {                       // 64 int4 loads
        s_off[t] = __ldg(&g_off[base + t]);
    } else if (t < 2 * PTS_PER_BLOCK) {            // 64 float4 loads
        s_w[t - PTS_PER_BLOCK] = __ldg(&g_w[base + t - PTS_PER_BLOCK]);
    }
    __syncthreads();                               // the ONLY barrier

    const int warp = t >> 5;   // 0..7
    const int lane = t & 31;
    const int off0 = lane * 4;
    const int off1 = 128 + lane * 4;

    #pragma unroll
    for (int it = 0; it < 4; it++) {
        #pragma unroll
        for (int i = 0; i < 2; i++) {
            const int li = it * 16 + warp * 2 + i;   // 0..63
            const int n  = base + li;                // NPTS % 64 == 0

            const int4   off = s_off[li];            // LDS broadcast
            const float4 w   = s_w[li];

            float4 a0 = make_float4(0.f, 0.f, 0.f, 0.f);
            float4 a1 = make_float4(0.f, 0.f, 0.f, 0.f);

            corner_acc(off.x, w.x, off0, off1, a0, a1);
            corner_acc(off.y, w.y, off0, off1, a0, a1);
            corner_acc(off.z, w.z, off0, off1, a0, a1);
            corner_acc(off.w, w.w, off0, off1, a0, a1);

            float4* orow = (float4*)(out + (size_t)n * OUTW);
            __stcs(&orow[16 + lane],      a0);
            __stcs(&orow[16 + 32 + lane], a1);
        }
    }
}

// ---------------------------------------------------------------------------
extern "C" void kernel_launch(void* const* d_in, const int* in_sizes, int n_in,
                              void* d_out, int out_size) {
    const float* points_mean = (const float*)d_in[0];
    // d_in[1] = mask (unused by reference)
    const float* voxel_feats = (const float*)d_in[2];
    const int*   coors       = (const int*)  d_in[3];
    const float* img_feats   = (const float*)d_in[4];
    const float* lidar2img   = (const float*)d_in[5];
    const int*   pad_shape   = (const int*)  d_in[6];
    float*       out         = (float*)d_out;

    // A: fused transpose + voxel copy + projection meta
    prep_kernel<<<TR_BLOCKS + VOX_BLOCKS + META_BLOCKS, 256>>>(
        img_feats, points_mean, coors, lidar2img, pad_shape, voxel_feats, out);

    // B: gather + point-feat write (block = 64 points, 4 barrier-free iters)
    gather_kernel<<<GATHER_BLOCKS, 256>>>(out);
}